// round 12
// baseline (speedup 1.0000x reference)
#include <cuda_runtime.h>
#include <cuda_bf16.h>

#define NQ 8
#define NL 4
#define BATCHN 4096
#define FULLMASK 0xffffffffu

// ---------------- f32x2 packed math helpers ----------------
__device__ __forceinline__ float2 f2fma(float2 a, float2 b, float2 c) {
    float2 d;
    asm("{\n\t"
        ".reg .b64 ra, rb, rc, rd;\n\t"
        "mov.b64 ra, {%2,%3};\n\t"
        "mov.b64 rb, {%4,%5};\n\t"
        "mov.b64 rc, {%6,%7};\n\t"
        "fma.rn.f32x2 rd, ra, rb, rc;\n\t"
        "mov.b64 {%0,%1}, rd;\n\t"
        "}"
        : "=f"(d.x), "=f"(d.y)
        : "f"(a.x), "f"(a.y), "f"(b.x), "f"(b.y), "f"(c.x), "f"(c.y));
    return d;
}
__device__ __forceinline__ float2 shflx2(float2 v, int m) {
    v.x = __shfl_xor_sync(FULLMASK, v.x, m);
    v.y = __shfl_xor_sync(FULLMASK, v.y, m);
    return v;
}

// State layout: ONE sample per 32 lanes, TWO samples per thread (independent
// register sets -> 2x ILP). 8 amplitudes per lane per sample packed as float2
// PR[4]/PI[4]; amplitude index = lane*8 + 2k + h.
// Qubit q <-> index bit (7-q):
//   q0->lane b4, q1->lane b3, q2->lane b2, q3->lane b1, q4->lane b0,
//   q5->k b1,    q6->k b0,    q7->packed half h.
// Rotations in TANGENT form; dropped cosines applied once as C^2 on <Z_0>.

__device__ __forceinline__ void ry_reg_t(float2* PR, float2* PI, float t, int ks) {
    float2 tp = make_float2(t, t), tn = make_float2(-t, -t);
#pragma unroll
    for (int k = 0; k < 4; k++) if (!(k & ks)) {
        const int k2 = k | ks;
        float2 r0 = PR[k], i0 = PI[k];
        PR[k]  = f2fma(tn, PR[k2], r0);
        PR[k2] = f2fma(tp, r0, PR[k2]);
        PI[k]  = f2fma(tn, PI[k2], i0);
        PI[k2] = f2fma(tp, i0, PI[k2]);
    }
}
__device__ __forceinline__ void ry_pk_t(float2* PR, float2* PI, float t) {
    float2 ts = make_float2(-t, t);
#pragma unroll
    for (int k = 0; k < 4; k++) {
        float2 r = PR[k], i = PI[k];
        PR[k] = f2fma(ts, make_float2(r.y, r.x), r);
        PI[k] = f2fma(ts, make_float2(i.y, i.x), i);
    }
}
__device__ __forceinline__ void ry_ln_t(float2* PR, float2* PI, float t, int lb, int lane) {
    const float ss = (lane & lb) ? t : -t;
    float2 t2 = make_float2(ss, ss);
#pragma unroll
    for (int k = 0; k < 4; k++) {
        float2 pr = shflx2(PR[k], lb);
        float2 pi = shflx2(PI[k], lb);
        PR[k] = f2fma(t2, pr, PR[k]);
        PI[k] = f2fma(t2, pi, PI[k]);
    }
}
__device__ __forceinline__ void rz_pk_t(float2* PR, float2* PI, float t) {
    float2 tp = make_float2(t, -t), tn = make_float2(-t, t);
#pragma unroll
    for (int k = 0; k < 4; k++) {
        float2 r = PR[k];
        PR[k] = f2fma(tp, PI[k], r);
        PI[k] = f2fma(tn, r, PI[k]);
    }
}
__device__ __forceinline__ void rz_reg_t(float2* PR, float2* PI, float t, int ks) {
    float2 tp = make_float2(t, t), tn = make_float2(-t, -t);
#pragma unroll
    for (int k = 0; k < 4; k++) {
        float2 a = (k & ks) ? tn : tp;
        float2 b = (k & ks) ? tp : tn;
        float2 r = PR[k];
        PR[k] = f2fma(a, PI[k], r);
        PI[k] = f2fma(b, r, PI[k]);
    }
}
__device__ __forceinline__ void rz_ln_t(float2* PR, float2* PI, float t, int lb, int lane) {
    const float g = (lane & lb) ? -t : t;
    float2 a = make_float2(g, g), b = make_float2(-g, -g);
#pragma unroll
    for (int k = 0; k < 4; k++) {
        float2 r = PR[k];
        PR[k] = f2fma(a, PI[k], r);
        PI[k] = f2fma(b, r, PI[k]);
    }
}

// Ring CNOTs i = 0..6 (i=7 is fused into the following RY(q0)).
__device__ __forceinline__ void ring_part(float2* PR, float2* PI, int lane, int src0123) {
    // i=0..3 composed (lane bits): one index shuffle
#pragma unroll
    for (int k = 0; k < 4; k++) {
        PR[k].x = __shfl_sync(FULLMASK, PR[k].x, src0123);
        PR[k].y = __shfl_sync(FULLMASK, PR[k].y, src0123);
        PI[k].x = __shfl_sync(FULLMASK, PI[k].x, src0123);
        PI[k].y = __shfl_sync(FULLMASK, PI[k].y, src0123);
    }
    // i=4: c=q4 (lane b0), t=q5 (k b1)
    if (lane & 1) {
        float2 t = PR[0]; PR[0] = PR[2]; PR[2] = t;
        t = PI[0]; PI[0] = PI[2]; PI[2] = t;
        t = PR[1]; PR[1] = PR[3]; PR[3] = t;
        t = PI[1]; PI[1] = PI[3]; PI[3] = t;
    }
    // i=5: c=q5 (k b1), t=q6 (k b0): swap k=2<->3
    {
        float2 t = PR[2]; PR[2] = PR[3]; PR[3] = t;
        t = PI[2]; PI[2] = PI[3]; PI[3] = t;
    }
    // i=6: c=q6 (k b0), t=q7 (half): swap halves for odd k
#pragma unroll
    for (int k = 1; k < 4; k += 2) {
        PR[k] = make_float2(PR[k].y, PR[k].x);
        PI[k] = make_float2(PI[k].y, PI[k].x);
    }
}

// Fused ring-i7 (c=q7 odd half, t=q0 lane b4) + RY(q0) tan form.
// With cur = pi7(old):  new.x = old.x + s*shfl(old.x),  new.y = shfl(old.y) + s*old.y
__device__ __forceinline__ void fused_i7_ry0(float2* PR, float2* PI, float t, int lane) {
    const float ss = (lane & 16) ? t : -t;
    float2 s2 = make_float2(ss, ss);
#pragma unroll
    for (int k = 0; k < 4; k++) {
        float prx = __shfl_xor_sync(FULLMASK, PR[k].x, 16);
        float pry = __shfl_xor_sync(FULLMASK, PR[k].y, 16);
        float pix = __shfl_xor_sync(FULLMASK, PI[k].x, 16);
        float piy = __shfl_xor_sync(FULLMASK, PI[k].y, 16);
        PR[k] = f2fma(s2, make_float2(prx, PR[k].y), make_float2(PR[k].x, pry));
        PI[k] = f2fma(s2, make_float2(pix, PI[k].y), make_float2(PI[k].x, piy));
    }
}

__global__ __launch_bounds__(256) void vqc_kernel(
    const float* __restrict__ x,      // (4096, 8)
    const float* __restrict__ w,      // (4, 8, 2)
    float* __restrict__ out)          // (4096,)
{
    __shared__ float wt[NL * NQ * 2];   // tan(w/2)
    __shared__ float wcs[NL * NQ * 2];  // cos(w/2)
    __shared__ float scale2;            // (prod of applied cos)^2
    const int tid = threadIdx.x;
    if (tid < NL * NQ * 2) {
        float a = 0.5f * w[tid];
        float s, c;
        sincosf(a, &s, &c);
        wt[tid]  = __fdividef(s, c);
        wcs[tid] = c;
    }
    __syncthreads();
    if (tid == 0) {
        float p = 1.0f;
#pragma unroll
        for (int i = 0; i < 49; i++) p *= wcs[i];
        scale2 = p * p;
    }
    __syncthreads();

    const int lane = tid & 31;
    const int gw = blockIdx.x * 8 + (tid >> 5);      // global warp id
    const int s0 = gw * 2, s1 = gw * 2 + 1;          // two samples per warp

    const int b4 = (lane >> 4) & 1, b3 = (lane >> 3) & 1, b2 = (lane >> 2) & 1,
              b1 = (lane >> 1) & 1, b0 = lane & 1;
    const int src0123 = (b4 << 4) | ((b3 ^ b4) << 3) | ((b2 ^ b3) << 2) |
                        ((b1 ^ b2) << 1) | (b0 ^ b1);

    // ---------- Angle encoding (product state, all-real) for both samples ----
    float2 PRa[4], PIa[4], PRb[4], PIb[4];
    {
        float cq[8], sq[8];
        const float4* xv = (const float4*)(x + s0 * NQ);
        float4 xa = __ldg(xv), xb = __ldg(xv + 1);
        float xs[8] = {xa.x, xa.y, xa.z, xa.w, xb.x, xb.y, xb.z, xb.w};
#pragma unroll
        for (int q = 0; q < 8; q++) __sincosf(0.5f * xs[q], &sq[q], &cq[q]);
        float A = (b4 ? sq[0] : cq[0]) * (b3 ? sq[1] : cq[1]) * (b2 ? sq[2] : cq[2]) *
                  (b1 ? sq[3] : cq[3]) * (b0 ? sq[4] : cq[4]);
        float u2[2], u4[4];
        u2[0] = A * cq[5];  u2[1] = A * sq[5];
#pragma unroll
        for (int k = 0; k < 4; k++) u4[k] = u2[k >> 1] * ((k & 1) ? sq[6] : cq[6]);
#pragma unroll
        for (int k = 0; k < 4; k++) {
            PRa[k] = make_float2(u4[k] * cq[7], u4[k] * sq[7]);
            PIa[k] = make_float2(0.0f, 0.0f);
        }
    }
    {
        float cq[8], sq[8];
        const float4* xv = (const float4*)(x + s1 * NQ);
        float4 xa = __ldg(xv), xb = __ldg(xv + 1);
        float xs[8] = {xa.x, xa.y, xa.z, xa.w, xb.x, xb.y, xb.z, xb.w};
#pragma unroll
        for (int q = 0; q < 8; q++) __sincosf(0.5f * xs[q], &sq[q], &cq[q]);
        float A = (b4 ? sq[0] : cq[0]) * (b3 ? sq[1] : cq[1]) * (b2 ? sq[2] : cq[2]) *
                  (b1 ? sq[3] : cq[3]) * (b0 ? sq[4] : cq[4]);
        float u2[2], u4[4];
        u2[0] = A * cq[5];  u2[1] = A * sq[5];
#pragma unroll
        for (int k = 0; k < 4; k++) u4[k] = u2[k >> 1] * ((k & 1) ? sq[6] : cq[6]);
#pragma unroll
        for (int k = 0; k < 4; k++) {
            PRb[k] = make_float2(u4[k] * cq[7], u4[k] * sq[7]);
            PIb[k] = make_float2(0.0f, 0.0f);
        }
    }

    // ---------------- Layers 0..2: ring + all rotations ----------------
#pragma unroll 1
    for (int l = 0; l < NL - 1; l++) {
        const int lbase = l * 16;
        ring_part(PRa, PIa, lane, src0123);
        ring_part(PRb, PIb, lane, src0123);
        // fused ring-i7 + RY(q0), then RZ(q0)
        {
            const float ty = wt[lbase], tz = wt[lbase + 1];
            fused_i7_ry0(PRa, PIa, ty, lane);
            fused_i7_ry0(PRb, PIb, ty, lane);
            rz_ln_t(PRa, PIa, tz, 16, lane);
            rz_ln_t(PRb, PIb, tz, 16, lane);
        }
#pragma unroll
        for (int i = 1; i < NQ; i++) {
            const float ty = wt[lbase + i * 2];
            const float tz = wt[lbase + i * 2 + 1];
            if (i < 5) {
                const int lb = 16 >> i;
                ry_ln_t(PRa, PIa, ty, lb, lane);
                ry_ln_t(PRb, PIb, ty, lb, lane);
                rz_ln_t(PRa, PIa, tz, lb, lane);
                rz_ln_t(PRb, PIb, tz, lb, lane);
            } else if (i == 7) {
                ry_pk_t(PRa, PIa, ty);
                ry_pk_t(PRb, PIb, ty);
                rz_pk_t(PRa, PIa, tz);
                rz_pk_t(PRb, PIb, tz);
            } else {
                const int ks = 1 << (6 - i);   // q5 -> 2, q6 -> 1
                ry_reg_t(PRa, PIa, ty, ks);
                ry_reg_t(PRb, PIb, ty, ks);
                rz_reg_t(PRa, PIa, tz, ks);
                rz_reg_t(PRb, PIb, tz, ks);
            }
        }
    }

    // ---------------- Layer 3: ring + RY(q0) only ----------------
    ring_part(PRa, PIa, lane, src0123);
    ring_part(PRb, PIb, lane, src0123);
    fused_i7_ry0(PRa, PIa, wt[3 * 16], lane);
    fused_i7_ry0(PRb, PIb, wt[3 * 16], lane);

    // ---------------- <Z_0>: q0 = lane bit4, scaled by C^2 ----------------
    float2 aa = make_float2(0.0f, 0.0f), ab = make_float2(0.0f, 0.0f);
#pragma unroll
    for (int k = 0; k < 4; k++) {
        aa = f2fma(PRa[k], PRa[k], aa);
        aa = f2fma(PIa[k], PIa[k], aa);
        ab = f2fma(PRb[k], PRb[k], ab);
        ab = f2fma(PIb[k], PIb[k], ab);
    }
    float acc0 = aa.x + aa.y, acc1 = ab.x + ab.y;
    if (lane & 16) { acc0 = -acc0; acc1 = -acc1; }
#pragma unroll
    for (int o = 1; o < 32; o <<= 1) {
        acc0 += __shfl_xor_sync(FULLMASK, acc0, o);
        acc1 += __shfl_xor_sync(FULLMASK, acc1, o);
    }
    if (lane == 0) {
        const float sc = scale2;
        out[s0] = acc0 * sc;
        out[s1] = acc1 * sc;
    }
}

extern "C" void kernel_launch(void* const* d_in, const int* in_sizes, int n_in,
                              void* d_out, int out_size) {
    const float* x = (const float*)d_in[0];   // (4096, 8)
    const float* w = (const float*)d_in[1];   // (4, 8, 2)
    float* out = (float*)d_out;               // (4096,)
    // 256 threads = 8 warps = 16 samples per block; 256 blocks, 2048 warps
    vqc_kernel<<<BATCHN / 16, 256>>>(x, w, out);
}

// round 15
// speedup vs baseline: 1.4775x; 1.4775x over previous
#include <cuda_runtime.h>
#include <cuda_bf16.h>

#define NQ 8
#define NL 4
#define BATCHN 4096
#define FULLMASK 0xffffffffu

// ---------------- f32x2 packed math helpers ----------------
__device__ __forceinline__ float2 f2fma(float2 a, float2 b, float2 c) {
    float2 d;
    asm("{\n\t"
        ".reg .b64 ra, rb, rc, rd;\n\t"
        "mov.b64 ra, {%2,%3};\n\t"
        "mov.b64 rb, {%4,%5};\n\t"
        "mov.b64 rc, {%6,%7};\n\t"
        "fma.rn.f32x2 rd, ra, rb, rc;\n\t"
        "mov.b64 {%0,%1}, rd;\n\t"
        "}"
        : "=f"(d.x), "=f"(d.y)
        : "f"(a.x), "f"(a.y), "f"(b.x), "f"(b.y), "f"(c.x), "f"(c.y));
    return d;
}
__device__ __forceinline__ float2 shflx2(float2 v, int m) {
    v.x = __shfl_xor_sync(FULLMASK, v.x, m);
    v.y = __shfl_xor_sync(FULLMASK, v.y, m);
    return v;
}
__device__ __forceinline__ int par5(int lane, int m) { return __popc(lane & m) & 1; }

// State layout: ONE sample per warp. 8 amplitudes per lane packed as float2
// PR[4]/PI[4]; amplitude index = label(lane)*8 + 2k + h.
// Qubit q <-> index bit (7-q):
//   q0..q4 -> LABEL bits 4..0 (lane bits, permuted implicitly by the ring),
//   q5->k b1, q6->k b0, q7->packed half h.
//
// The ring CNOTs i=0..3 form a linear lane-bit permutation M. We never move
// data for them; instead label(lane) = M^r * lane after r rings. Lane-bit
// gates then use compile-time partner masks M^{-r} e_b and sign masks
// row_b(M^r). row_4(M^r) = 16 for all r, so q0's sign is always lane bit 4.
// Rotations in TANGENT form; dropped cosines applied once as C^2 on <Z_0>.

// RY(tan) on a k-bit (q5: ks=2, q6: ks=1)
__device__ __forceinline__ void ry_reg_t(float2* PR, float2* PI, float t, int ks) {
    float2 tp = make_float2(t, t), tn = make_float2(-t, -t);
#pragma unroll
    for (int k = 0; k < 4; k++) if (!(k & ks)) {
        const int k2 = k | ks;
        float2 r0 = PR[k], i0 = PI[k];
        PR[k]  = f2fma(tn, PR[k2], r0);
        PR[k2] = f2fma(tp, r0, PR[k2]);
        PI[k]  = f2fma(tn, PI[k2], i0);
        PI[k2] = f2fma(tp, i0, PI[k2]);
    }
}
// RY(tan) on q7 (packed halves)
__device__ __forceinline__ void ry_pk_t(float2* PR, float2* PI, float t) {
    float2 ts = make_float2(-t, t);
#pragma unroll
    for (int k = 0; k < 4; k++) {
        float2 r = PR[k], i = PI[k];
        PR[k] = f2fma(ts, make_float2(r.y, r.x), r);
        PI[k] = f2fma(ts, make_float2(i.y, i.x), i);
    }
}
// RY(tan) on a label bit: partner mask pm, sign bit sgn (this lane's label bit)
__device__ __forceinline__ void ry_lbl_t(float2* PR, float2* PI, float t, int pm, int sgn) {
    const float ss = sgn ? t : -t;
    float2 t2 = make_float2(ss, ss);
#pragma unroll
    for (int k = 0; k < 4; k++) {
        float2 pr = shflx2(PR[k], pm);
        float2 pi = shflx2(PI[k], pm);
        PR[k] = f2fma(t2, pr, PR[k]);
        PI[k] = f2fma(t2, pi, PI[k]);
    }
}
// RZ(tan) on q7
__device__ __forceinline__ void rz_pk_t(float2* PR, float2* PI, float t) {
    float2 tp = make_float2(t, -t), tn = make_float2(-t, t);
#pragma unroll
    for (int k = 0; k < 4; k++) {
        float2 r = PR[k];
        PR[k] = f2fma(tp, PI[k], r);
        PI[k] = f2fma(tn, r, PI[k]);
    }
}
// RZ(tan) on a k-bit
__device__ __forceinline__ void rz_reg_t(float2* PR, float2* PI, float t, int ks) {
    float2 tp = make_float2(t, t), tn = make_float2(-t, -t);
#pragma unroll
    for (int k = 0; k < 4; k++) {
        float2 a = (k & ks) ? tn : tp;
        float2 b = (k & ks) ? tp : tn;
        float2 r = PR[k];
        PR[k] = f2fma(a, PI[k], r);
        PI[k] = f2fma(b, r, PI[k]);
    }
}
// RZ(tan) on a label bit: diagonal, only needs the sign bit
__device__ __forceinline__ void rz_lbl_t(float2* PR, float2* PI, float t, int sgn) {
    const float g = sgn ? -t : t;
    float2 a = make_float2(g, g), b = make_float2(-g, -g);
#pragma unroll
    for (int k = 0; k < 4; k++) {
        float2 r = PR[k];
        PR[k] = f2fma(a, PI[k], r);
        PI[k] = f2fma(b, r, PI[k]);
    }
}

// Ring CNOTs i=4..7. i=0..3 are implicit (relabeling).
// ctrl  = this lane's label bit0 (q4 control) AFTER relabel = par5(lane, ROW0)
// pm4   = partner mask of label bit4 at this ring count (for i=7's q0 target)
__device__ __forceinline__ void ring_rest(float2* PR, float2* PI, int ctrl, int pm4) {
    // i=4: c=q4 (label b0), t=q5 (k b1): swap k<->k+2 where control set
    if (ctrl) {
        float2 t = PR[0]; PR[0] = PR[2]; PR[2] = t;
        t = PI[0]; PI[0] = PI[2]; PI[2] = t;
        t = PR[1]; PR[1] = PR[3]; PR[3] = t;
        t = PI[1]; PI[1] = PI[3]; PI[3] = t;
    }
    // i=5: c=q5 (k b1), t=q6 (k b0): swap k=2<->3
    {
        float2 t = PR[2]; PR[2] = PR[3]; PR[3] = t;
        t = PI[2]; PI[2] = PI[3]; PI[3] = t;
    }
    // i=6: c=q6 (k b0), t=q7 (half): swap halves for odd k
#pragma unroll
    for (int k = 1; k < 4; k += 2) {
        PR[k] = make_float2(PR[k].y, PR[k].x);
        PI[k] = make_float2(PI[k].y, PI[k].x);
    }
    // i=7: c=q7 (odd half .y), t=q0 (label b4): only .y moves, partner pm4
#pragma unroll
    for (int k = 0; k < 4; k++) {
        PR[k].y = __shfl_xor_sync(FULLMASK, PR[k].y, pm4);
        PI[k].y = __shfl_xor_sync(FULLMASK, PI[k].y, pm4);
    }
}

__global__ __launch_bounds__(256) void vqc_kernel(
    const float* __restrict__ x,      // (4096, 8)
    const float* __restrict__ w,      // (4, 8, 2)
    float* __restrict__ out)          // (4096,)
{
    __shared__ float wt[NL * NQ * 2];   // tan(w/2)
    __shared__ float wcs[NL * NQ * 2];  // cos(w/2)
    __shared__ float scale2;            // (prod of applied cos)^2
    const int tid = threadIdx.x;
    if (tid < NL * NQ * 2) {
        float a = 0.5f * w[tid];
        float s, c;
        sincosf(a, &s, &c);
        wt[tid]  = __fdividef(s, c);
        wcs[tid] = c;
    }
    __syncthreads();
    if (tid == 0) {
        float p = 1.0f;
#pragma unroll
        for (int i = 0; i < 49; i++) p *= wcs[i];
        scale2 = p * p;
    }
    __syncthreads();

    const int lane = tid & 31;
    const int sample = blockIdx.x * 8 + (tid >> 5);   // one sample per warp
    const int b4 = (lane >> 4) & 1, b3 = (lane >> 3) & 1, b2 = (lane >> 2) & 1,
              b1 = (lane >> 1) & 1, b0 = lane & 1;

    // Per-layer constants, ring count r = l+1.
    // Partner masks M^{-r} e_b and sign-rows row_b(M^r), hand-derived & checked:
    //   M^{-1}: m -> m ^ (m>>1);  row_b(M^{r+1}) = XOR_{k>=b} row_k(M^r)
    static constexpr int PB4[4]  = {24, 20, 30, 17};   // q0 partner
    static constexpr int PB3[3]  = {12, 10, 15};       // q1 partner
    static constexpr int PB2[3]  = { 6,  5,  7};       // q2 partner
    static constexpr int PB1[3]  = { 3,  2,  3};       // q3 partner
    static constexpr int ROW3[3] = {24,  8, 24};       // q1 sign row
    static constexpr int ROW2[3] = {28, 20, 12};       // q2 sign row
    static constexpr int ROW1[3] = {30, 10,  6};       // q3 sign row
    static constexpr int ROW0[4] = {31, 21, 19, 17};   // q4 sign row (also i=4 ctrl)
    // row4(M^r) == 16 for all r: q0 sign is always lane bit 4.

    // ---------- Angle encoding as direct product state (all-real) ----------
    float cq[8], sq[8];
    {
        const float4* xv = (const float4*)(x + sample * NQ);
        float4 xa = __ldg(xv), xb = __ldg(xv + 1);
        float xs[8] = {xa.x, xa.y, xa.z, xa.w, xb.x, xb.y, xb.z, xb.w};
#pragma unroll
        for (int q = 0; q < 8; q++) __sincosf(0.5f * xs[q], &sq[q], &cq[q]);
    }
    float A = (b4 ? sq[0] : cq[0]) * (b3 ? sq[1] : cq[1]) * (b2 ? sq[2] : cq[2]) *
              (b1 ? sq[3] : cq[3]) * (b0 ? sq[4] : cq[4]);
    float u2[2], u4[4];
    u2[0] = A * cq[5];  u2[1] = A * sq[5];
#pragma unroll
    for (int k = 0; k < 4; k++) u4[k] = u2[k >> 1] * ((k & 1) ? sq[6] : cq[6]);

    float2 PR[4], PI[4];
#pragma unroll
    for (int k = 0; k < 4; k++) {
        PR[k] = make_float2(u4[k] * cq[7], u4[k] * sq[7]);
        PI[k] = make_float2(0.0f, 0.0f);
    }

    // ---------------- Layers 0..2: ring + all rotations ----------------
#pragma unroll
    for (int l = 0; l < NL - 1; l++) {
        // ring i=0..3 implicit (relabel); i=4..7 explicit:
        ring_rest(PR, PI, par5(lane, ROW0[l]), PB4[l]);

        const int lbase = l * 16;
        // per-layer label-bit signs (shared by the RY/RZ pair of each qubit)
        const int s0g = b4;                       // q0: row4 == 16 always
        const int s1g = par5(lane, ROW3[l]);      // q1
        const int s2g = par5(lane, ROW2[l]);      // q2
        const int s3g = par5(lane, ROW1[l]);      // q3
        const int s4g = par5(lane, ROW0[l]);      // q4

        ry_lbl_t(PR, PI, wt[lbase +  0], PB4[l], s0g);
        rz_lbl_t(PR, PI, wt[lbase +  1], s0g);
        ry_lbl_t(PR, PI, wt[lbase +  2], PB3[l], s1g);
        rz_lbl_t(PR, PI, wt[lbase +  3], s1g);
        ry_lbl_t(PR, PI, wt[lbase +  4], PB2[l], s2g);
        rz_lbl_t(PR, PI, wt[lbase +  5], s2g);
        ry_lbl_t(PR, PI, wt[lbase +  6], PB1[l], s3g);
        rz_lbl_t(PR, PI, wt[lbase +  7], s3g);
        ry_lbl_t(PR, PI, wt[lbase +  8], 1, s4g);   // q4 partner mask is always 1
        rz_lbl_t(PR, PI, wt[lbase +  9], s4g);
        ry_reg_t(PR, PI, wt[lbase + 10], 2);        // q5
        rz_reg_t(PR, PI, wt[lbase + 11], 2);
        ry_reg_t(PR, PI, wt[lbase + 12], 1);        // q6
        rz_reg_t(PR, PI, wt[lbase + 13], 1);
        ry_pk_t(PR, PI, wt[lbase + 14]);            // q7
        rz_pk_t(PR, PI, wt[lbase + 15]);
    }

    // ---------------- Layer 3: ring + RY(q0) only ----------------
    // Final-layer rotations on qubits != q0 preserve the q0 marginal; the
    // diagonal RZ(q0) preserves |amp|^2 -> no effect on <Z_0>.
    ring_rest(PR, PI, par5(lane, ROW0[3]), PB4[3]);
    ry_lbl_t(PR, PI, wt[3 * 16], PB4[3], b4);

    // ---------------- <Z_0>: q0 label bit4, sign = lane bit4 always --------
    float2 a2 = make_float2(0.0f, 0.0f);
#pragma unroll
    for (int k = 0; k < 4; k++) {
        a2 = f2fma(PR[k], PR[k], a2);
        a2 = f2fma(PI[k], PI[k], a2);
    }
    float acc = a2.x + a2.y;
    if (lane & 16) acc = -acc;
    acc += __shfl_xor_sync(FULLMASK, acc, 1);
    acc += __shfl_xor_sync(FULLMASK, acc, 2);
    acc += __shfl_xor_sync(FULLMASK, acc, 4);
    acc += __shfl_xor_sync(FULLMASK, acc, 8);
    acc += __shfl_xor_sync(FULLMASK, acc, 16);
    if (lane == 0) out[sample] = acc * scale2;
}

extern "C" void kernel_launch(void* const* d_in, const int* in_sizes, int n_in,
                              void* d_out, int out_size) {
    const float* x = (const float*)d_in[0];   // (4096, 8)
    const float* w = (const float*)d_in[1];   // (4, 8, 2)
    float* out = (float*)d_out;               // (4096,)
    // 256 threads = 8 warps = 8 samples per block; 512 blocks, 4096 warps
    vqc_kernel<<<BATCHN / 8, 256>>>(x, w, out);
}